// round 14
// baseline (speedup 1.0000x reference)
#include <cuda_runtime.h>

#define TT     512
#define CHUNK  16
#define NPAIR  8
#define NCHUNK 32
#define NBH    64
#define ROWP   68

__device__ float g_Wsnap[(size_t)NBH * NCHUNK * 4096];
__device__ float g_bsnap[(size_t)NBH * NCHUNK * 64];
__device__ int   g_prog[NBH];

#define CPA16(saddr, gptr) \
    asm volatile("cp.async.cg.shared.global [%0], [%1], 16;" :: "r"(saddr), "l"(gptr))
#define CPCOMMIT() asm volatile("cp.async.commit_group;")
#define CPWAIT0()  asm volatile("cp.async.wait_group 0;")

// chunk-role dyn smem layout (floats)
#define OFF_XQ  4096                  // 4 buffers x 1088
#define OFF_XK  (OFF_XQ + 4352)
#define OFF_GZ  (OFF_XK + 4352)
#define OFF_BB  (OFF_GZ + 1088)
#define OFF_ETA (OFF_BB + 64)         // 4 x 16
#define SMF     (OFF_ETA + 64)        // 14016 floats = 56 KB

__global__ void reset_kernel() {
    if (threadIdx.x < NBH) g_prog[threadIdx.x] = 0;
}

// ======== scan role: pipelined rank-1 scan with deferred fix ================
// 5 warps: warp 0 = LN/serial specialist; warps 1-4 hold W rows in registers.
// One barrier per step. Critical path = warp0's combine->fix->LN chain only.
__device__ __forceinline__
void scan_role(float* sm, int bh,
               const float* __restrict__ XK, const float* __restrict__ XV,
               const float* __restrict__ W1, const float* __restrict__ b1,
               const float* __restrict__ gam, const float* __restrict__ bet)
{
    float* const xs = sm;            // [4][64]  xk15 ring
    float* const vs = sm + 256;      // [4][64]  xv15 ring
    float* const pz = sm + 512;      // [2][4][64] matvec partials
    float* const gs = sm + 1024;     // [2][64]  el*gz (pre-scaled)

    const int tid  = threadIdx.x;    // < 160
    const int lane = tid & 31;
    const int w    = tid >> 5;       // 0..4
    const int h    = bh & 15;

    float Wa[16], Wb[16];
    if (w >= 1) {
        const float* Wg = W1 + (size_t)h * 4096;
        #pragma unroll
        for (int i = 0; i < 16; i++) {
            const int d = (w-1)*16 + i;
            Wa[i] = Wg[d*64 + lane];
            Wb[i] = Wg[d*64 + lane + 32];
        }
    }
    float bav = 0.f, bbv = 0.f, ga = 0.f, gb = 0.f, bea = 0.f, beb = 0.f;
    if (w == 0) {
        bav = b1[h*64 + lane]; bbv = b1[h*64 + lane + 32];
        ga  = gam[h*64 + lane]; gb  = gam[h*64 + lane + 32];
        bea = bet[h*64 + lane]; beb = bet[h*64 + lane + 32];
    }

    const size_t base = (size_t)bh * (TT * 1024) + 960;   // row 15 of each step
    const float* xkg = XK + base;
    const float* xvg = XV + base;

    // ---- prologue: stage x0,x1,v0,v1; zero x_{-1} slot and gs parity 1 ----
    if (tid < 64) {
        xs[tid]       = xkg[tid];        vs[tid]       = xvg[tid];
        xs[64 + tid]  = xkg[1024 + tid]; vs[64 + tid]  = xvg[1024 + tid];
        xs[192 + tid] = 0.f;             // x_{-1} (slot 3)
        gs[64 + tid]  = 0.f;             // gs parity 1 (step -1)
    }
    __syncthreads();
    // matvec partials for token 0 (vs W_0) -> pz[0]
    if (w >= 1) {
        float za = 0.f, zb = 0.f;
        #pragma unroll
        for (int i = 0; i < 16; i++) {
            const float xd = xs[(w-1)*16 + i];
            za = fmaf(xd, Wa[i], za);
            zb = fmaf(xd, Wb[i], zb);
        }
        pz[(w-1)*64 + lane] = za; pz[(w-1)*64 + lane + 32] = zb;
    }
    __syncthreads();

    float Dprev = 0.f;
    for (int t = 0; t <= 496; t++) {
        const int par = t & 1;

        // issue global loads for x_{t+2} early
        float xl = 0.f, vl = 0.f;
        if (tid < 64 && t + 2 < TT) {
            xl = xkg[(size_t)(t+2)*1024 + tid];
            vl = xvg[(size_t)(t+2)*1024 + tid];
        }

        if (w >= 1) {
            // (1) rank-1 update with gs_{t-1} (pre-scaled) and x_{t-1}
            const float* gsp = gs + (par^1)*64;
            const float gfa = gsp[lane], gfb = gsp[lane + 32];
            const float* xm = xs + ((t+3)&3)*64;
            #pragma unroll
            for (int i = 0; i < 16; i++) {
                const float xd = xm[(w-1)*16 + i];
                Wa[i] = fmaf(-xd, gfa, Wa[i]);
                Wb[i] = fmaf(-xd, gfb, Wb[i]);
            }
            // (2) snapshot at chunk boundary (W has updates <= t-1)
            if ((t & 15) == 0) {
                float* ws = g_Wsnap + ((size_t)bh * NCHUNK + (t >> 4)) * 4096;
                #pragma unroll
                for (int i = 0; i < 16; i++) {
                    const int d = (w-1)*16 + i;
                    ws[d*64 + lane]      = Wa[i];
                    ws[d*64 + lane + 32] = Wb[i];
                }
            }
            // (3) matvec partials for token t+1 (lagged W; fixed next step)
            const float* xn = xs + ((t+1)&3)*64;
            float za = 0.f, zb = 0.f;
            #pragma unroll
            for (int i = 0; i < 16; i++) {
                const float xd = xn[(w-1)*16 + i];
                za = fmaf(xd, Wa[i], za);
                zb = fmaf(xd, Wb[i], zb);
            }
            float* pzd = pz + ((t+1)&1)*256 + (w-1)*64;
            pzd[lane] = za; pzd[lane + 32] = zb;
        } else {
            // publish flag for the snapshot written last step (after barrier)
            if (lane == 0 && t >= 1 && ((t-1) & 15) == 0) {
                __threadfence();
                atomicExch(&g_prog[bh], ((t-1) >> 4) + 1);
            }
            // b snapshot (state <= t-1)
            if ((t & 15) == 0) {
                float* bs = g_bsnap + ((size_t)bh * NCHUNK + (t >> 4)) * 64;
                bs[lane] = bav; bs[lane + 32] = bbv;
            }
            // combine z_t partials + current b, then deferred fix
            const float* pzc = pz + par*256;
            float za = bav + ((pzc[lane] + pzc[64+lane]) + (pzc[128+lane] + pzc[192+lane]));
            float zb = bbv + ((pzc[lane+32] + pzc[64+lane+32]) + (pzc[128+lane+32] + pzc[192+lane+32]));
            const float* gsp = gs + (par^1)*64;
            za = fmaf(-Dprev, gsp[lane],      za);
            zb = fmaf(-Dprev, gsp[lane + 32], zb);
            // bundled reductions: LN sums + next dot + ||x_t||^2
            const float xa  = xs[(t&3)*64 + lane],     xb  = xs[(t&3)*64 + lane + 32];
            const float xna = xs[((t+1)&3)*64 + lane], xnb = xs[((t+1)&3)*64 + lane + 32];
            float s1 = za + zb;
            float s2 = za*za + zb*zb;
            float Dn = xa*xna + xb*xnb;
            float ss = xa*xa + xb*xb;
            #pragma unroll
            for (int m = 16; m >= 1; m >>= 1) {
                s1 += __shfl_xor_sync(~0u, s1, m);
                s2 += __shfl_xor_sync(~0u, s2, m);
                Dn += __shfl_xor_sync(~0u, Dn, m);
                ss += __shfl_xor_sync(~0u, ss, m);
            }
            const float el  = 0.01f / (1.0f + fmaxf(sqrtf(ss), 1e-6f));
            const float mu  = s1 * 0.015625f;
            const float var = fmaf(-mu, mu, s2 * 0.015625f);
            const float r   = rsqrtf(var + 1e-6f);
            const float va = vs[(t&3)*64 + lane], vb = vs[(t&3)*64 + lane + 32];
            const float gza = 2.0f * (fmaf(ga, (za-mu)*r, bea) - va + xa);
            const float gzb = 2.0f * (fmaf(gb, (zb-mu)*r, beb) - vb + xb);
            gs[par*64 + lane]      = el * gza;
            gs[par*64 + lane + 32] = el * gzb;
            bav = fmaf(-el, gza, bav);
            bbv = fmaf(-el, gzb, bbv);
            Dprev = Dn;
        }

        // stage x_{t+2}, v_{t+2} into the ring (slot (t+2)&3 is dead this step)
        if (tid < 64 && t + 2 < TT) {
            xs[((t+2)&3)*64 + tid] = xl;
            vs[((t+2)&3)*64 + tid] = vl;
        }
        __syncthreads();
    }
    if (tid == 0) { __threadfence(); atomicExch(&g_prog[bh], NCHUNK + 1); }
}

// ====== chunk role: parallel chunk replay, paired steps (unchanged) =========
__device__ __forceinline__
void chunk_role(float* sm, int c, int bh,
                const float* __restrict__ XQ, const float* __restrict__ XK,
                const float* __restrict__ XV, const float* __restrict__ gam,
                const float* __restrict__ bet, float* __restrict__ out)
{
    float* const W  = sm;
    float* const GZ = sm + OFF_GZ;
    float* const BB = sm + OFF_BB;

    const int tid = threadIdx.x;
    const int h   = bh & 15;
    const int k   = tid >> 4;
    const int q   = tid & 15;
    const int f0  = q << 2;
    const int sl  = k*ROWP + f0;

    if (tid == 0) {
        volatile int* f = &g_prog[bh];
        while (*f < c + 1) __nanosleep(256);
    }
    __syncthreads();
    __threadfence();

    const size_t base = (size_t)bh * (TT * 1024) + (size_t)c * (CHUNK * 1024);
    const float* xqg = XQ + base;
    const float* xkg = XK + base;
    const float* xvg = XV + base;
    float*       og  = out + base;

    {
        const float* Ws = g_Wsnap + ((size_t)bh * NCHUNK + c) * 4096;
        #pragma unroll
        for (int i = 0; i < 4; i++)
            *(float4*)&W[i*1024 + tid*4] = *(const float4*)&Ws[i*1024 + tid*4];
        if (tid < 16) {
            const float* bs = g_bsnap + ((size_t)bh * NCHUNK + c) * 64;
            *(float4*)&BB[tid*4] = *(const float4*)&bs[tid*4];
        }
    }
    const float4 g4  = *(const float4*)&gam[h*64 + f0];
    const float4 be4 = *(const float4*)&bet[h*64 + f0];

    #pragma unroll
    for (int s = 0; s < 2; s++) {
        const float4 tq = *(const float4*)&xqg[s*1024 + tid*4];
        const float4 tk = *(const float4*)&xkg[s*1024 + tid*4];
        *(float4*)&sm[OFF_XQ + s*1088 + sl] = tq;
        *(float4*)&sm[OFF_XK + s*1088 + sl] = tk;
        float ss = tk.x*tk.x + tk.y*tk.y + tk.z*tk.z + tk.w*tk.w;
        #pragma unroll
        for (int m = 8; m >= 1; m >>= 1) ss += __shfl_xor_sync(~0u, ss, m, 16);
        if (q == 0) sm[OFF_ETA + s*16 + k] = 0.01f / (1.0f + fmaxf(sqrtf(ss), 1e-6f));
    }
    __syncthreads();

    for (int p = 0; p < NPAIR; p++) {
        const int bA = (p & 1) * 2, bB = bA + 1;
        const int nA = ((p + 1) & 1) * 2, nB = nA + 1;
        const float* xqA  = sm + OFF_XQ + bA*1088;
        const float* xkA_ = sm + OFF_XK + bA*1088;
        const float* xqB  = sm + OFF_XQ + bB*1088;
        const float* xkB  = sm + OFF_XK + bB*1088;

        if (p + 1 < NPAIR) {
            const size_t o1 = (size_t)(2*p+2)*1024 + tid*4;
            const size_t o2 = o1 + 1024;
            CPA16((unsigned)__cvta_generic_to_shared(&sm[OFF_XQ + nA*1088 + sl]), xqg + o1);
            CPA16((unsigned)__cvta_generic_to_shared(&sm[OFF_XK + nA*1088 + sl]), xkg + o1);
            CPA16((unsigned)__cvta_generic_to_shared(&sm[OFF_XQ + nB*1088 + sl]), xqg + o2);
            CPA16((unsigned)__cvta_generic_to_shared(&sm[OFF_XK + nB*1088 + sl]), xkg + o2);
            CPCOMMIT();
        }
        const float4 cv  = *(const float4*)&xvg[(size_t)(2*p)*1024 + tid*4];
        const float4 cv1 = *(const float4*)&xvg[(size_t)(2*p+1)*1024 + tid*4];

        float em, el, em1, el1;
        {
            const float4 e0 = *(const float4*)&sm[OFF_ETA + bA*16 + 0];
            const float4 e1 = *(const float4*)&sm[OFF_ETA + bA*16 + 4];
            const float4 e2 = *(const float4*)&sm[OFF_ETA + bA*16 + 8];
            const float4 e3 = *(const float4*)&sm[OFF_ETA + bA*16 + 12];
            em = ((e0.x+e0.y+e0.z+e0.w) + (e1.x+e1.y+e1.z+e1.w)
                + (e2.x+e2.y+e2.z+e2.w) + (e3.x+e3.y+e3.z+e3.w)) * (1.0f/16.0f);
            el = e3.w;
            const float4 f0v = *(const float4*)&sm[OFF_ETA + bB*16 + 0];
            const float4 f1v = *(const float4*)&sm[OFF_ETA + bB*16 + 4];
            const float4 f2v = *(const float4*)&sm[OFF_ETA + bB*16 + 8];
            const float4 f3v = *(const float4*)&sm[OFF_ETA + bB*16 + 12];
            em1 = ((f0v.x+f0v.y+f0v.z+f0v.w) + (f1v.x+f1v.y+f1v.z+f1v.w)
                 + (f2v.x+f2v.y+f2v.z+f2v.w) + (f3v.x+f3v.y+f3v.z+f3v.w)) * (1.0f/16.0f);
            el1 = f3v.w;
        }

        float4 z, zd, zn, zdn;
        {
            const float4 b4 = *(const float4*)&BB[f0];
            z = b4; zd = b4; zn = b4; zdn = b4;
        }
        float a = 1.0f, an = 1.0f, dk = 0.f, dq = 0.f;
        #pragma unroll 4
        for (int j = 0; j < 16; j++) {
            const int d0 = j << 2;
            const float4 xkt = *(const float4*)&xkA_[k*ROWP + d0];
            const float4 xqt = *(const float4*)&xqA [k*ROWP + d0];
            const float4 xkn = *(const float4*)&xkB [k*ROWP + d0];
            const float4 xqn = *(const float4*)&xqB [k*ROWP + d0];
            const float4 xAt = *(const float4*)&xkA_[q*ROWP + d0];
            const float4 xAn = *(const float4*)&xkB [q*ROWP + d0];
            const float4 xF  = *(const float4*)&xkA_[15*ROWP + d0];
            a  = fmaf(xqt.x, xAt.x, fmaf(xqt.y, xAt.y, fmaf(xqt.z, xAt.z, fmaf(xqt.w, xAt.w, a))));
            an = fmaf(xqn.x, xAn.x, fmaf(xqn.y, xAn.y, fmaf(xqn.z, xAn.z, fmaf(xqn.w, xAn.w, an))));
            dk = fmaf(xkn.x, xF.x, fmaf(xkn.y, xF.y, fmaf(xkn.z, xF.z, fmaf(xkn.w, xF.w, dk))));
            dq = fmaf(xqn.x, xF.x, fmaf(xqn.y, xF.y, fmaf(xqn.z, xF.z, fmaf(xqn.w, xF.w, dq))));
            #pragma unroll
            for (int i = 0; i < 4; i++) {
                const float4 w4 = *(const float4*)&W[(d0+i)*64 + f0];
                const float kt  = (&xkt.x)[i], qt  = (&xqt.x)[i];
                const float kn2 = (&xkn.x)[i], qn2 = (&xqn.x)[i];
                z.x   = fmaf(kt,  w4.x, z.x);   z.y   = fmaf(kt,  w4.y, z.y);
                z.z   = fmaf(kt,  w4.z, z.z);   z.w   = fmaf(kt,  w4.w, z.w);
                zd.x  = fmaf(qt,  w4.x, zd.x);  zd.y  = fmaf(qt,  w4.y, zd.y);
                zd.z  = fmaf(qt,  w4.z, zd.z);  zd.w  = fmaf(qt,  w4.w, zd.w);
                zn.x  = fmaf(kn2, w4.x, zn.x);  zn.y  = fmaf(kn2, w4.y, zn.y);
                zn.z  = fmaf(kn2, w4.z, zn.z);  zn.w  = fmaf(kn2, w4.w, zn.w);
                zdn.x = fmaf(qn2, w4.x, zdn.x); zdn.y = fmaf(qn2, w4.y, zdn.y);
                zdn.z = fmaf(qn2, w4.z, zdn.z); zdn.w = fmaf(qn2, w4.w, zdn.w);
            }
        }

        const float4 ck = *(const float4*)&xkA_[sl];
        {
            float s1 = z.x + z.y + z.z + z.w;
            float s2 = z.x*z.x + z.y*z.y + z.z*z.z + z.w*z.w;
            #pragma unroll
            for (int m = 8; m >= 1; m >>= 1) {
                s1 += __shfl_xor_sync(~0u, s1, m, 16);
                s2 += __shfl_xor_sync(~0u, s2, m, 16);
            }
            const float mu  = s1 * 0.015625f;
            const float var = fmaf(-mu, mu, s2 * 0.015625f);
            const float r   = rsqrtf(var + 1e-6f);
            float4 gz;
            gz.x = 2.0f * (fmaf(g4.x, (z.x-mu)*r, be4.x) - cv.x + ck.x);
            gz.y = 2.0f * (fmaf(g4.y, (z.y-mu)*r, be4.y) - cv.y + ck.y);
            gz.z = 2.0f * (fmaf(g4.z, (z.z-mu)*r, be4.z) - cv.z + ck.z);
            gz.w = 2.0f * (fmaf(g4.w, (z.w-mu)*r, be4.w) - cv.w + ck.w);
            *(float4*)&GZ[sl] = gz;
        }
        __syncthreads();

        const float4 gl = *(const float4*)&GZ[15*ROWP + f0];
        {
            const float fk  = -el * (dk + 1.0f);
            const float fq2 = -el * (dq + 1.0f);
            zn.x  = fmaf(fk,  gl.x, zn.x);  zn.y  = fmaf(fk,  gl.y, zn.y);
            zn.z  = fmaf(fk,  gl.z, zn.z);  zn.w  = fmaf(fk,  gl.w, zn.w);
            zdn.x = fmaf(fq2, gl.x, zdn.x); zdn.y = fmaf(fq2, gl.y, zdn.y);
            zdn.z = fmaf(fq2, gl.z, zdn.z); zdn.w = fmaf(fq2, gl.w, zdn.w);
        }
        {
            float4 cc = make_float4(0.f,0.f,0.f,0.f);
            #pragma unroll
            for (int kp = 0; kp < 16; kp++) {
                const float av  = __shfl_sync(~0u, a, kp, 16);
                const float4 gv = *(const float4*)&GZ[kp*ROWP + f0];
                cc.x = fmaf(av, gv.x, cc.x); cc.y = fmaf(av, gv.y, cc.y);
                cc.z = fmaf(av, gv.z, cc.z); cc.w = fmaf(av, gv.w, cc.w);
            }
            zd.x = fmaf(-em, cc.x, zd.x); zd.y = fmaf(-em, cc.y, zd.y);
            zd.z = fmaf(-em, cc.z, zd.z); zd.w = fmaf(-em, cc.w, zd.w);
            float t1 = zd.x + zd.y + zd.z + zd.w;
            float t2 = zd.x*zd.x + zd.y*zd.y + zd.z*zd.z + zd.w*zd.w;
            #pragma unroll
            for (int m = 8; m >= 1; m >>= 1) {
                t1 += __shfl_xor_sync(~0u, t1, m, 16);
                t2 += __shfl_xor_sync(~0u, t2, m, 16);
            }
            const float mu2  = t1 * 0.015625f;
            const float var2 = fmaf(-mu2, mu2, t2 * 0.015625f);
            const float r2   = rsqrtf(var2 + 1e-6f);
            const float4 cq = *(const float4*)&xqA[sl];
            float4 o;
            o.x = cq.x + fmaf(g4.x, (zd.x-mu2)*r2, be4.x);
            o.y = cq.y + fmaf(g4.y, (zd.y-mu2)*r2, be4.y);
            o.z = cq.z + fmaf(g4.z, (zd.z-mu2)*r2, be4.z);
            o.w = cq.w + fmaf(g4.w, (zd.w-mu2)*r2, be4.w);
            *(float4*)&og[(size_t)(2*p)*1024 + tid*4] = o;
        }
        __syncthreads();

        const float4 ck1 = *(const float4*)&xkB[sl];
        {
            float s1 = zn.x + zn.y + zn.z + zn.w;
            float s2 = zn.x*zn.x + zn.y*zn.y + zn.z*zn.z + zn.w*zn.w;
            #pragma unroll
            for (int m = 8; m >= 1; m >>= 1) {
                s1 += __shfl_xor_sync(~0u, s1, m, 16);
                s2 += __shfl_xor_sync(~0u, s2, m, 16);
            }
            const float mu  = s1 * 0.015625f;
            const float var = fmaf(-mu, mu, s2 * 0.015625f);
            const float r   = rsqrtf(var + 1e-6f);
            float4 gz;
            gz.x = 2.0f * (fmaf(g4.x, (zn.x-mu)*r, be4.x) - cv1.x + ck1.x);
            gz.y = 2.0f * (fmaf(g4.y, (zn.y-mu)*r, be4.y) - cv1.y + ck1.y);
            gz.z = 2.0f * (fmaf(g4.z, (zn.z-mu)*r, be4.z) - cv1.z + ck1.z);
            gz.w = 2.0f * (fmaf(g4.w, (zn.w-mu)*r, be4.w) - cv1.w + ck1.w);
            *(float4*)&GZ[sl] = gz;
        }
        __syncthreads();
        {
            float4 cc = make_float4(0.f,0.f,0.f,0.f);
            #pragma unroll
            for (int kp = 0; kp < 16; kp++) {
                const float av  = __shfl_sync(~0u, an, kp, 16);
                const float4 gv = *(const float4*)&GZ[kp*ROWP + f0];
                cc.x = fmaf(av, gv.x, cc.x); cc.y = fmaf(av, gv.y, cc.y);
                cc.z = fmaf(av, gv.z, cc.z); cc.w = fmaf(av, gv.w, cc.w);
            }
            zdn.x = fmaf(-em1, cc.x, zdn.x); zdn.y = fmaf(-em1, cc.y, zdn.y);
            zdn.z = fmaf(-em1, cc.z, zdn.z); zdn.w = fmaf(-em1, cc.w, zdn.w);
            float t1 = zdn.x + zdn.y + zdn.z + zdn.w;
            float t2 = zdn.x*zdn.x + zdn.y*zdn.y + zdn.z*zdn.z + zdn.w*zdn.w;
            #pragma unroll
            for (int m = 8; m >= 1; m >>= 1) {
                t1 += __shfl_xor_sync(~0u, t1, m, 16);
                t2 += __shfl_xor_sync(~0u, t2, m, 16);
            }
            const float mu2  = t1 * 0.015625f;
            const float var2 = fmaf(-mu2, mu2, t2 * 0.015625f);
            const float r2   = rsqrtf(var2 + 1e-6f);
            const float4 cq1 = *(const float4*)&xqB[sl];
            float4 o;
            o.x = cq1.x + fmaf(g4.x, (zdn.x-mu2)*r2, be4.x);
            o.y = cq1.y + fmaf(g4.y, (zdn.y-mu2)*r2, be4.y);
            o.z = cq1.z + fmaf(g4.z, (zdn.z-mu2)*r2, be4.z);
            o.w = cq1.w + fmaf(g4.w, (zdn.w-mu2)*r2, be4.w);
            *(float4*)&og[(size_t)(2*p+1)*1024 + tid*4] = o;
        }

        if (p + 1 < NPAIR) {
            const float4 gl1 = *(const float4*)&GZ[15*ROWP + f0];
            #pragma unroll
            for (int jj = 0; jj < 4; jj++) {
                const int d = k + 16*jj;
                const float cf  = -el  * xkA_[15*ROWP + d];
                const float cf1 = -el1 * xkB [15*ROWP + d];
                float4 w4 = *(float4*)&W[d*64 + f0];
                w4.x = fmaf(cf, gl.x, fmaf(cf1, gl1.x, w4.x));
                w4.y = fmaf(cf, gl.y, fmaf(cf1, gl1.y, w4.y));
                w4.z = fmaf(cf, gl.z, fmaf(cf1, gl1.z, w4.z));
                w4.w = fmaf(cf, gl.w, fmaf(cf1, gl1.w, w4.w));
                *(float4*)&W[d*64 + f0] = w4;
            }
            if (tid < 16) {
                float4 bv = *(float4*)&BB[f0];
                bv.x = fmaf(-el, gl.x, fmaf(-el1, gl1.x, bv.x));
                bv.y = fmaf(-el, gl.y, fmaf(-el1, gl1.y, bv.y));
                bv.z = fmaf(-el, gl.z, fmaf(-el1, gl1.z, bv.z));
                bv.w = fmaf(-el, gl.w, fmaf(-el1, gl1.w, bv.w));
                *(float4*)&BB[f0] = bv;
            }
            CPWAIT0();
            #pragma unroll
            for (int s = 0; s < 2; s++) {
                const int nb = (s == 0) ? nA : nB;
                const float4 tk = *(const float4*)&sm[OFF_XK + nb*1088 + sl];
                float ss = tk.x*tk.x + tk.y*tk.y + tk.z*tk.z + tk.w*tk.w;
                #pragma unroll
                for (int m = 8; m >= 1; m >>= 1) ss += __shfl_xor_sync(~0u, ss, m, 16);
                if (q == 0) sm[OFF_ETA + nb*16 + k] = 0.01f / (1.0f + fmaxf(sqrtf(ss), 1e-6f));
            }
            __syncthreads();
        }
    }
}

// ============================ fused kernel ==================================
__global__ __launch_bounds__(256, 3)
void fused_kernel(const float* __restrict__ XQ, const float* __restrict__ XK,
                  const float* __restrict__ XV, const float* __restrict__ W1,
                  const float* __restrict__ b1, const float* __restrict__ gam,
                  const float* __restrict__ bet, float* __restrict__ out)
{
    extern __shared__ float sm[];
    const int bid = blockIdx.x;

    if (bid < NBH) {
        if (threadIdx.x >= 160) return;     // scan role uses 5 warps
        scan_role(sm, bid, XK, XV, W1, b1, gam, bet);
        return;
    }
    const int cid = bid - NBH;
    const int c   = cid >> 6;      // chunk-major: early waves need early chunks
    const int bh  = cid & 63;
    chunk_role(sm, c, bh, XQ, XK, XV, gam, bet, out);
}

extern "C" void kernel_launch(void* const* d_in, const int* in_sizes, int n_in,
                              void* d_out, int out_size) {
    const float* XQ  = (const float*)d_in[0];
    const float* XK  = (const float*)d_in[1];
    const float* XV  = (const float*)d_in[2];
    const float* W1  = (const float*)d_in[3];
    const float* b1  = (const float*)d_in[4];
    const float* gam = (const float*)d_in[5];
    const float* bet = (const float*)d_in[6];
    float* out = (float*)d_out;

    const int smem = SMF * (int)sizeof(float);       // ~56 KB
    static int configured = 0;
    if (!configured) {
        cudaFuncSetAttribute(fused_kernel, cudaFuncAttributeMaxDynamicSharedMemorySize, smem);
        configured = 1;
    }
    reset_kernel<<<1, 64>>>();
    fused_kernel<<<NBH + NBH * NCHUNK, 256, smem>>>(XQ, XK, XV, W1, b1, gam, bet, out);
}